// round 16
// baseline (speedup 1.0000x reference)
#include <cuda_runtime.h>
#include <cuda_bf16.h>
#include <math_constants.h>
#include <cstdint>

// Problem constants
#define BATCH   2
#define SEQ     2048
#define HIDDEN  1024
#define HEADS   16
#define HEAD_D  64
#define QKV_N   (3 * HIDDEN)          // 3072
#define M_TOT   (BATCH * SEQ)         // 4096
#define KDIM    1024
#define ATTN_SCALE 125.0f             // TEMP_K / sqrt(HEAD_D)
#define BH_TOT  (BATCH * HEADS)       // 32
#define ATT_ELEMS (BH_TOT * SEQ * HEAD_D)
#define NROWS   (BH_TOT * SEQ)        // 65536
#define CAND_MARGIN 30.0f             // logit-units candidate threshold
#define MAX_CAND 24

// ---------------------------------------------------------------------------
// Scratch (__device__ globals per allocation-free rule)
// ---------------------------------------------------------------------------
__device__ float g_qkv[M_TOT * QKV_N];
__device__ __nv_bfloat16 g_x_hi[M_TOT * HIDDEN];
__device__ __nv_bfloat16 g_x_mid[M_TOT * HIDDEN];
__device__ __nv_bfloat16 g_c_hi[M_TOT * HIDDEN];
__device__ __nv_bfloat16 g_c_mid[M_TOT * HIDDEN];
__device__ __nv_bfloat16 g_wq_hi[QKV_N * KDIM];
__device__ __nv_bfloat16 g_wq_mid[QKV_N * KDIM];
__device__ __nv_bfloat16 g_wo_hi[HIDDEN * KDIM];
__device__ __nv_bfloat16 g_wo_mid[HIDDEN * KDIM];
__device__ __nv_bfloat16 g_aq_hi[ATT_ELEMS];   // [bh][s][64] q*125 bf16-hi
__device__ __nv_bfloat16 g_ak_hi[ATT_ELEMS];   // [bh][s][64] k bf16-hi
__device__ int g_cnt[NROWS];
__device__ int g_cand[NROWS * MAX_CAND];

// ---------------------------------------------------------------------------
__device__ __forceinline__ uint32_t smem_u32(const void* p) {
    uint32_t a;
    asm("{ .reg .u64 t; cvta.to.shared.u64 t, %1; cvt.u32.u64 %0, t; }"
        : "=r"(a) : "l"(p));
    return a;
}

__device__ __forceinline__ void cp16(uint32_t dst, const void* src) {
    asm volatile("cp.async.cg.shared.global [%0], [%1], 16;"
                 :: "r"(dst), "l"(src) : "memory");
}
#define CP_COMMIT() asm volatile("cp.async.commit_group;" ::: "memory")
#define CP_WAIT(n)  asm volatile("cp.async.wait_group %0;" :: "n"(n) : "memory")

__device__ __forceinline__ void ldsm4(uint32_t* r, uint32_t addr) {
    asm volatile("ldmatrix.sync.aligned.m8n8.x4.shared.b16 {%0,%1,%2,%3}, [%4];"
                 : "=r"(r[0]), "=r"(r[1]), "=r"(r[2]), "=r"(r[3]) : "r"(addr));
}

__device__ __forceinline__ void mma16816(float* c, const uint32_t* a,
                                         const uint32_t* b) {
    asm volatile(
        "mma.sync.aligned.m16n8k16.row.col.f32.bf16.bf16.f32 "
        "{%0,%1,%2,%3}, {%4,%5,%6,%7}, {%8,%9}, {%0,%1,%2,%3};"
        : "+f"(c[0]), "+f"(c[1]), "+f"(c[2]), "+f"(c[3])
        : "r"(a[0]), "r"(a[1]), "r"(a[2]), "r"(a[3]), "r"(b[0]), "r"(b[1]));
}

__device__ __forceinline__ void store_split2(__nv_bfloat16* hi,
                                             __nv_bfloat16* mid,
                                             size_t off, float a, float b) {
    __nv_bfloat162 h;
    h.x = __float2bfloat16_rn(a);
    h.y = __float2bfloat16_rn(b);
    *(__nv_bfloat162*)(hi + off) = h;
    __nv_bfloat162 m2 = __floats2bfloat162_rn(a - __bfloat162float(h.x),
                                              b - __bfloat162float(h.y));
    *(__nv_bfloat162*)(mid + off) = m2;
}

// ---------------------------------------------------------------------------
// Prepass 0: zero candidate counters.
// ---------------------------------------------------------------------------
__global__ __launch_bounds__(256)
void zero_cnt(int* __restrict__ cnt)
{
    int i = blockIdx.x * 256 + threadIdx.x;
    if (i < NROWS) cnt[i] = 0;
}

// ---------------------------------------------------------------------------
// Prepass 1: elementwise fp32 -> bf16 (hi, mid) split.
// ---------------------------------------------------------------------------
__global__ __launch_bounds__(256)
void split_rows(const float4* __restrict__ src,
                __nv_bfloat162* __restrict__ hi,
                __nv_bfloat162* __restrict__ mid, int n4)
{
    int i = blockIdx.x * blockDim.x + threadIdx.x;
    if (i >= n4) return;
    float4 v = src[i];
    __nv_bfloat16 h0 = __float2bfloat16_rn(v.x);
    __nv_bfloat16 h1 = __float2bfloat16_rn(v.y);
    __nv_bfloat16 h2 = __float2bfloat16_rn(v.z);
    __nv_bfloat16 h3 = __float2bfloat16_rn(v.w);
    __nv_bfloat16 m0 = __float2bfloat16_rn(v.x - __bfloat162float(h0));
    __nv_bfloat16 m1 = __float2bfloat16_rn(v.y - __bfloat162float(h1));
    __nv_bfloat16 m2 = __float2bfloat16_rn(v.z - __bfloat162float(h2));
    __nv_bfloat16 m3 = __float2bfloat16_rn(v.w - __bfloat162float(h3));
    __nv_bfloat162 a, b, c, d;
    a.x = h0; a.y = h1; b.x = h2; b.y = h3;
    c.x = m0; c.y = m1; d.x = m2; d.y = m3;
    hi[2 * i] = a;  hi[2 * i + 1] = b;
    mid[2 * i] = c; mid[2 * i + 1] = d;
}

// ---------------------------------------------------------------------------
// Prepass 2: W [K x N] fp32 -> W^T [N x K] bf16 (hi, mid).
// ---------------------------------------------------------------------------
__global__ __launch_bounds__(256)
void split_transpose(const float* __restrict__ W,
                     __nv_bfloat16* __restrict__ hi,
                     __nv_bfloat16* __restrict__ mid, int K, int N)
{
    __shared__ float s[32][33];
    int n0 = blockIdx.x * 32;
    int k0 = blockIdx.y * 32;
    int tx = threadIdx.x, ty = threadIdx.y;
    #pragma unroll
    for (int i = 0; i < 4; i++) {
        int kk = ty + 8 * i;
        s[kk][tx] = W[(size_t)(k0 + kk) * N + n0 + tx];
    }
    __syncthreads();
    #pragma unroll
    for (int i = 0; i < 4; i++) {
        int nn = ty + 8 * i;
        float v = s[tx][nn];
        __nv_bfloat16 h = __float2bfloat16_rn(v);
        __nv_bfloat16 m = __float2bfloat16_rn(v - __bfloat162float(h));
        size_t o = (size_t)(n0 + nn) * KDIM + k0 + tx;
        hi[o] = h;
        mid[o] = m;
    }
}

// ---------------------------------------------------------------------------
// Prepass 3 (slim): qkv fp32 -> bf16-hi Q (x125) and K only.
// ---------------------------------------------------------------------------
__global__ __launch_bounds__(256)
void attn_prep2(const float* __restrict__ qkv,
                __nv_bfloat16* __restrict__ qh, __nv_bfloat16* __restrict__ kh)
{
    int st = blockIdx.x * 64;
    int h  = blockIdx.y;
    int b  = blockIdx.z;
    int bh = b * HEADS + h;
    int t  = threadIdx.x;
    #pragma unroll
    for (int i = 0; i < 16; i++) {
        int e   = t + 256 * i;       // 0..4095
        int row = e >> 6;
        int d   = e & 63;
        const float* base = qkv + (size_t)(b * SEQ + st + row) * QKV_N + h * HEAD_D + d;
        size_t o = ((size_t)bh * SEQ + st + row) * HEAD_D + d;
        qh[o] = __float2bfloat16_rn(base[0] * ATTN_SCALE);
        kh[o] = __float2bfloat16_rn(base[HIDDEN]);
    }
}

// ---------------------------------------------------------------------------
// mma.sync split-bf16 GEMM (exact round-14 version: measured 239us QKV).
// ---------------------------------------------------------------------------
#define GBM 128
#define GBN 128
#define GBK 32
#define ROWB 80
#define TILE_SZ (128 * ROWB)
#define STAGE_SZ (4 * TILE_SZ)
#define SMEM_MMA (2 * STAGE_SZ)

__device__ __forceinline__ void load_tile_async(uint32_t dst,
                                                const __nv_bfloat16* src,
                                                int row0, int k0, int t)
{
    #pragma unroll
    for (int f = t; f < 512; f += 256) {
        int row = f >> 2, q = f & 3;
        cp16(dst + row * ROWB + q * 16,
             src + (size_t)(row0 + row) * KDIM + k0 + q * 8);
    }
}

__global__ __launch_bounds__(256, 2)
void mma_gemm(const __nv_bfloat16* __restrict__ Ahi,
              const __nv_bfloat16* __restrict__ Amid,
              const __nv_bfloat16* __restrict__ Bhi,
              const __nv_bfloat16* __restrict__ Bmid,
              const float* __restrict__ bias, float* __restrict__ C, int ldN)
{
    extern __shared__ char smraw[];
    uint32_t sb = smem_u32(smraw);

    int t    = threadIdx.x;
    int lane = t & 31;
    int wid  = t >> 5;
    int wm   = wid & 3;
    int wn   = wid >> 2;
    int m0   = blockIdx.y * GBM;
    int n0   = blockIdx.x * GBN;

    int g  = lane >> 3;
    int lr = lane & 7;
    int aRow = ((g & 1) << 3) + lr;
    int aCol = (g >> 1) << 4;
    int bRow = ((g >> 1) << 3) + lr;
    int bCol = (g & 1) << 4;

    float c[2][8][4];
    #pragma unroll
    for (int mi = 0; mi < 2; mi++)
        #pragma unroll
        for (int ng = 0; ng < 8; ng++)
            #pragma unroll
            for (int j = 0; j < 4; j++) c[mi][ng][j] = 0.0f;

    const int NCH = KDIM / GBK;

    {
        uint32_t st = sb;
        load_tile_async(st,               Ahi,  m0, 0, t);
        load_tile_async(st + TILE_SZ,     Amid, m0, 0, t);
        load_tile_async(st + 2 * TILE_SZ, Bhi,  n0, 0, t);
        load_tile_async(st + 3 * TILE_SZ, Bmid, n0, 0, t);
        CP_COMMIT();
    }

    #pragma unroll 1
    for (int i = 0; i < NCH; i++) {
        uint32_t cur = sb + (i & 1) * STAGE_SZ;
        if (i + 1 < NCH) {
            uint32_t nst = sb + ((i + 1) & 1) * STAGE_SZ;
            int k0 = (i + 1) * GBK;
            load_tile_async(nst,               Ahi,  m0, k0, t);
            load_tile_async(nst + TILE_SZ,     Amid, m0, k0, t);
            load_tile_async(nst + 2 * TILE_SZ, Bhi,  n0, k0, t);
            load_tile_async(nst + 3 * TILE_SZ, Bmid, n0, k0, t);
            CP_COMMIT();
            CP_WAIT(1);
        } else {
            CP_WAIT(0);
        }
        __syncthreads();

        uint32_t AhiB = cur;
        uint32_t AmdB = cur + TILE_SZ;
        uint32_t BhiB = cur + 2 * TILE_SZ;
        uint32_t BmdB = cur + 3 * TILE_SZ;

        #pragma unroll
        for (int ks = 0; ks < 2; ks++) {
            int kb = ks * 32;
            uint32_t aH[2][4], aM[2][4];
            #pragma unroll
            for (int mi = 0; mi < 2; mi++)
                ldsm4(aH[mi], AhiB + (wm * 32 + mi * 16 + aRow) * ROWB + kb + aCol);
            #pragma unroll
            for (int mi = 0; mi < 2; mi++)
                ldsm4(aM[mi], AmdB + (wm * 32 + mi * 16 + aRow) * ROWB + kb + aCol);

            #pragma unroll
            for (int nh = 0; nh < 2; nh++) {
                uint32_t bH[2][4], bM[2][4];
                #pragma unroll
                for (int nb = 0; nb < 2; nb++)
                    ldsm4(bH[nb], BhiB + (wn * 64 + nh * 32 + nb * 16 + bRow) * ROWB + kb + bCol);
                #pragma unroll
                for (int nb = 0; nb < 2; nb++)
                    ldsm4(bM[nb], BmdB + (wn * 64 + nh * 32 + nb * 16 + bRow) * ROWB + kb + bCol);

                #pragma unroll
                for (int mi = 0; mi < 2; mi++)
                    #pragma unroll
                    for (int ng = 0; ng < 4; ng++)
                        mma16816(c[mi][nh * 4 + ng], aH[mi],
                                 &bH[ng >> 1][(ng & 1) * 2]);
                #pragma unroll
                for (int mi = 0; mi < 2; mi++)
                    #pragma unroll
                    for (int ng = 0; ng < 4; ng++)
                        mma16816(c[mi][nh * 4 + ng], aH[mi],
                                 &bM[ng >> 1][(ng & 1) * 2]);
                #pragma unroll
                for (int mi = 0; mi < 2; mi++)
                    #pragma unroll
                    for (int ng = 0; ng < 4; ng++)
                        mma16816(c[mi][nh * 4 + ng], aM[mi],
                                 &bH[ng >> 1][(ng & 1) * 2]);
            }
        }
        __syncthreads();
    }

    int r  = lane >> 2;
    int cg = (lane & 3) * 2;
    #pragma unroll
    for (int mi = 0; mi < 2; mi++) {
        #pragma unroll
        for (int ng = 0; ng < 8; ng++) {
            int gn  = n0 + wn * 64 + ng * 8 + cg;
            float2 bb = *(const float2*)(bias + gn);
            int gm  = m0 + wm * 32 + mi * 16 + r;
            float2 o0, o1;
            o0.x = c[mi][ng][0] + bb.x;  o0.y = c[mi][ng][1] + bb.y;
            o1.x = c[mi][ng][2] + bb.x;  o1.y = c[mi][ng][3] + bb.y;
            *(float2*)(C + (size_t)gm * ldN + gn)       = o0;
            *(float2*)(C + (size_t)(gm + 8) * ldN + gn) = o1;
        }
    }
}

// ---------------------------------------------------------------------------
// Attention phase 1 (single pass): hh-logit scan with inline candidate
// flagging against the RUNNING row max. Since running_max <= final_max,
// every true candidate (s >= final_max - margin) is flagged when scanned
// -> flagged set is a superset; exact-fp32 gather neutralizes false flags.
// No revisit pass, no tile-max cache.
// ---------------------------------------------------------------------------
#define AP 144
#define SQ_SZ  (128 * AP)              // 18432 (Q hi)
#define SK_SZ  (64 * AP)               // 9216 per K tile
#define SO_K0   SQ_SZ
#define SO_K1   (SQ_SZ + SK_SZ)
#define SMEM_SCAN (SQ_SZ + 2 * SK_SZ)

__device__ __forceinline__ void load_k_tile(uint32_t dst,
    const __nv_bfloat16* kh, int bh, int k0, int t)
{
    #pragma unroll
    for (int i = 0; i < 2; i++) {
        int f = t + 256 * i;
        int row = f >> 3, ch = f & 7;
        cp16(dst + row * AP + ch * 16,
             kh + ((size_t)bh * SEQ + k0 + row) * HEAD_D + ch * 8);
    }
}

__global__ __launch_bounds__(256)
void attn_scan(const __nv_bfloat16* __restrict__ qhp,
               const __nv_bfloat16* __restrict__ khp)
{
    extern __shared__ char smraw[];
    uint32_t sb = smem_u32(smraw);

    int qt = (int)gridDim.x - 1 - (int)blockIdx.x;
    int h  = blockIdx.y;
    int b  = blockIdx.z;
    int bh = b * HEADS + h;
    int q0 = qt * 128;
    int t    = threadIdx.x;
    int lane = t & 31;
    int wid  = t >> 5;

    int g  = lane >> 3;
    int lr = lane & 7;
    int aRow = ((g & 1) << 3) + lr;
    int aCol = (g >> 1) << 4;
    int bRow = ((g >> 1) << 3) + lr;
    int bCol = (g & 1) << 4;

    // load Q hi
    {
        const __nv_bfloat16* p = qhp + ((size_t)bh * SEQ + q0) * HEAD_D;
        #pragma unroll
        for (int i = 0; i < 4; i++) {
            int f = t + 256 * i;
            int row = f >> 3, chq = f & 7;
            cp16(sb + row * AP + chq * 16, p + row * HEAD_D + chq * 8);
        }
        CP_COMMIT();
    }
    load_k_tile(sb + SO_K0, khp, bh, 0, t);
    CP_COMMIT();
    CP_WAIT(1);
    __syncthreads();

    uint32_t qfh[4][4];
    #pragma unroll
    for (int ks = 0; ks < 4; ks++)
        ldsm4(qfh[ks], sb + (wid * 16 + aRow) * AP + ks * 32 + aCol);

    float m0 = -CUDART_INF_F, m1 = -CUDART_INF_F;   // per-row running max
    int r0g  = q0 + wid * 16 + (lane >> 2);
    int rtop = q0 + wid * 16 + 15;
    int grow0 = bh * SEQ + r0g;
    int grow1 = grow0 + 8;
    const int nkt = qt * 2 + 2;

    #pragma unroll 1
    for (int kt = 0; kt < nkt; kt++) {
        uint32_t cur = sb + ((kt & 1) ? SO_K1 : SO_K0);
        if (kt + 1 < nkt) {
            load_k_tile(sb + (((kt + 1) & 1) ? SO_K1 : SO_K0), khp, bh,
                        (kt + 1) * 64, t);
            CP_COMMIT();
            CP_WAIT(1);
        } else {
            CP_WAIT(0);
        }
        __syncthreads();

        if (kt * 64 <= rtop) {           // warp-uniform: not fully masked
            float s[8][4];
            #pragma unroll
            for (int nb = 0; nb < 8; nb++)
                #pragma unroll
                for (int j = 0; j < 4; j++) s[nb][j] = 0.0f;
            #pragma unroll
            for (int ks = 0; ks < 4; ks++) {
                uint32_t bk[4][4];
                #pragma unroll
                for (int n4 = 0; n4 < 4; n4++)
                    ldsm4(bk[n4], cur + (n4 * 16 + bRow) * AP + ks * 32 + bCol);
                #pragma unroll
                for (int nb = 0; nb < 8; nb++)
                    mma16816(s[nb], qfh[ks], &bk[nb >> 1][(nb & 1) * 2]);
            }
            if (kt * 64 + 63 > q0 + wid * 16) {
                #pragma unroll
                for (int nb = 0; nb < 8; nb++) {
                    int gc = kt * 64 + nb * 8 + (lane & 3) * 2;
                    if (gc + 0 > r0g)     s[nb][0] = -CUDART_INF_F;
                    if (gc + 1 > r0g)     s[nb][1] = -CUDART_INF_F;
                    if (gc + 0 > r0g + 8) s[nb][2] = -CUDART_INF_F;
                    if (gc + 1 > r0g + 8) s[nb][3] = -CUDART_INF_F;
                }
            }
            // update running row maxes
            float tm0 = -CUDART_INF_F, tm1 = -CUDART_INF_F;
            #pragma unroll
            for (int nb = 0; nb < 8; nb++) {
                tm0 = fmaxf(tm0, fmaxf(s[nb][0], s[nb][1]));
                tm1 = fmaxf(tm1, fmaxf(s[nb][2], s[nb][3]));
            }
            tm0 = fmaxf(tm0, __shfl_xor_sync(0xffffffffu, tm0, 1));
            tm0 = fmaxf(tm0, __shfl_xor_sync(0xffffffffu, tm0, 2));
            tm1 = fmaxf(tm1, __shfl_xor_sync(0xffffffffu, tm1, 1));
            tm1 = fmaxf(tm1, __shfl_xor_sync(0xffffffffu, tm1, 2));
            m0 = fmaxf(m0, tm0);
            m1 = fmaxf(m1, tm1);

            // flag candidates vs running max (superset of true candidates)
            float th0 = m0 - CAND_MARGIN;
            float th1 = m1 - CAND_MARGIN;
            #pragma unroll
            for (int nb = 0; nb < 8; nb++) {
                int kbase = kt * 64 + nb * 8 + (lane & 3) * 2;
                if (s[nb][0] >= th0) {
                    int idx = atomicAdd(&g_cnt[grow0], 1);
                    if (idx < MAX_CAND) g_cand[grow0 * MAX_CAND + idx] = kbase;
                }
                if (s[nb][1] >= th0) {
                    int idx = atomicAdd(&g_cnt[grow0], 1);
                    if (idx < MAX_CAND) g_cand[grow0 * MAX_CAND + idx] = kbase + 1;
                }
                if (s[nb][2] >= th1) {
                    int idx = atomicAdd(&g_cnt[grow1], 1);
                    if (idx < MAX_CAND) g_cand[grow1 * MAX_CAND + idx] = kbase;
                }
                if (s[nb][3] >= th1) {
                    int idx = atomicAdd(&g_cnt[grow1], 1);
                    if (idx < MAX_CAND) g_cand[grow1 * MAX_CAND + idx] = kbase + 1;
                }
            }
        }
        __syncthreads();
    }
}

// ---------------------------------------------------------------------------
// Attention phase 2: exact fp32 softmax over candidates.
// One warp per query row; <=24 candidates; writes ctx as bf16 hi/mid.
// ---------------------------------------------------------------------------
__global__ __launch_bounds__(256)
void attn_gather(const float* __restrict__ qkv,
                 __nv_bfloat16* __restrict__ ch,
                 __nv_bfloat16* __restrict__ cm)
{
    int w    = (blockIdx.x * 256 + threadIdx.x) >> 5;   // global row
    int lane = threadIdx.x & 31;
    int bh = w >> 11;
    int sq = w & (SEQ - 1);
    int b  = bh >> 4;
    int h  = bh & 15;

    const float* qb = qkv + ((size_t)(b * SEQ + sq)) * QKV_N + h * HEAD_D;
    float q0 = qb[lane * 2]     * ATTN_SCALE;
    float q1 = qb[lane * 2 + 1] * ATTN_SCALE;

    int cnt = g_cnt[w];
    if (cnt > MAX_CAND) cnt = MAX_CAND;

    size_t off = (size_t)(b * SEQ + sq) * HIDDEN + h * HEAD_D + lane * 2;
    if (cnt <= 0) {              // defensive (argmax key always flagged)
        store_split2(ch, cm, off, 0.0f, 0.0f);
        return;
    }

    // load + sort candidate indices (determinism; insertion sort, n<=24)
    int cd[MAX_CAND];
    #pragma unroll
    for (int i = 0; i < MAX_CAND; i++)
        cd[i] = (i < cnt) ? g_cand[w * MAX_CAND + i] : 0x7fffffff;
    #pragma unroll
    for (int i = 1; i < MAX_CAND; i++) {
        int key = cd[i];
        #pragma unroll
        for (int j = i - 1; j >= 0; j--) {
            if (cd[j] > key) { cd[j + 1] = cd[j]; cd[j] = key; key = cd[j]; }
        }
    }

    // exact logits
    float sv[MAX_CAND];
    #pragma unroll
    for (int i = 0; i < MAX_CAND; i++) {
        float p = -CUDART_INF_F;
        if (i < cnt) {
            const float* kb = qkv + ((size_t)(b * SEQ + cd[i])) * QKV_N
                            + HIDDEN + h * HEAD_D;
            p = q0 * kb[lane * 2] + q1 * kb[lane * 2 + 1];
            p += __shfl_xor_sync(0xffffffffu, p, 16);
            p += __shfl_xor_sync(0xffffffffu, p, 8);
            p += __shfl_xor_sync(0xffffffffu, p, 4);
            p += __shfl_xor_sync(0xffffffffu, p, 2);
            p += __shfl_xor_sync(0xffffffffu, p, 1);
        }
        sv[i] = p;
    }

    float mx = -CUDART_INF_F;
    #pragma unroll
    for (int i = 0; i < MAX_CAND; i++) mx = fmaxf(mx, sv[i]);

    float l = 0.0f, o0 = 0.0f, o1 = 0.0f;
    #pragma unroll
    for (int i = 0; i < MAX_CAND; i++) {
        if (i < cnt) {
            float pe = __expf(sv[i] - mx);
            l += pe;
            const float* vb = qkv + ((size_t)(b * SEQ + cd[i])) * QKV_N
                            + 2 * HIDDEN + h * HEAD_D;
            o0 += pe * vb[lane * 2];
            o1 += pe * vb[lane * 2 + 1];
        }
    }
    float inv = 1.0f / l;
    store_split2(ch, cm, off, o0 * inv, o1 * inv);
}

// ---------------------------------------------------------------------------
extern "C" void kernel_launch(void* const* d_in, const int* in_sizes, int n_in,
                              void* d_out, int out_size)
{
    const float* x     = (const float*)d_in[0];
    const float* W_qkv = (const float*)d_in[1];
    const float* b_qkv = (const float*)d_in[2];
    const float* W_out = (const float*)d_in[3];
    const float* b_out = (const float*)d_in[4];
    float* out = (float*)d_out;

    float *qkv;
    __nv_bfloat16 *x_hi, *x_mid, *c_hi, *c_mid, *wq_hi, *wq_mid, *wo_hi, *wo_mid;
    __nv_bfloat16 *aqh, *akh;
    int* cnt_ptr;
    cudaGetSymbolAddress((void**)&qkv,    g_qkv);
    cudaGetSymbolAddress((void**)&x_hi,   g_x_hi);
    cudaGetSymbolAddress((void**)&x_mid,  g_x_mid);
    cudaGetSymbolAddress((void**)&c_hi,   g_c_hi);
    cudaGetSymbolAddress((void**)&c_mid,  g_c_mid);
    cudaGetSymbolAddress((void**)&wq_hi,  g_wq_hi);
    cudaGetSymbolAddress((void**)&wq_mid, g_wq_mid);
    cudaGetSymbolAddress((void**)&wo_hi,  g_wo_hi);
    cudaGetSymbolAddress((void**)&wo_mid, g_wo_mid);
    cudaGetSymbolAddress((void**)&aqh,    g_aq_hi);
    cudaGetSymbolAddress((void**)&akh,    g_ak_hi);
    cudaGetSymbolAddress((void**)&cnt_ptr, g_cnt);

    cudaFuncSetAttribute(mma_gemm, cudaFuncAttributeMaxDynamicSharedMemorySize,
                         SMEM_MMA);
    cudaFuncSetAttribute(attn_scan, cudaFuncAttributeMaxDynamicSharedMemorySize,
                         SMEM_SCAN);

    // 0) zero candidate counters
    zero_cnt<<<(NROWS + 255) / 256, 256>>>(cnt_ptr);
    // 1) split x -> bf16 hi/mid
    {
        int n4 = M_TOT * HIDDEN / 4;
        split_rows<<<(n4 + 255) / 256, 256>>>((const float4*)x,
                                              (__nv_bfloat162*)x_hi,
                                              (__nv_bfloat162*)x_mid, n4);
    }
    // 2) transpose+split W_qkv
    split_transpose<<<dim3(QKV_N / 32, KDIM / 32), dim3(32, 8)>>>(
        W_qkv, wq_hi, wq_mid, KDIM, QKV_N);
    // 3) QKV projection (tensor cores, 2 CTAs/SM — round-14 schedule)
    mma_gemm<<<dim3(QKV_N / GBN, M_TOT / GBM), 256, SMEM_MMA>>>(
        x_hi, x_mid, wq_hi, wq_mid, b_qkv, qkv, QKV_N);
    // 4) prep bf16-hi Q/K
    attn_prep2<<<dim3(SEQ / 64, HEADS, BATCH), 256>>>(qkv, aqh, akh);
    // 5) phase 1: single-pass scan + candidate flagging
    attn_scan<<<dim3(SEQ / 128, HEADS, BATCH), 256, SMEM_SCAN>>>(aqh, akh);
    // 6) phase 2: exact softmax over candidates -> ctx hi/mid
    attn_gather<<<NROWS / 8, 256>>>(qkv, c_hi, c_mid);
    // 7) transpose+split W_out
    split_transpose<<<dim3(HIDDEN / 32, KDIM / 32), dim3(32, 8)>>>(
        W_out, wo_hi, wo_mid, KDIM, HIDDEN);
    // 8) output projection (tensor cores, 2 CTAs/SM)
    mma_gemm<<<dim3(HIDDEN / GBN, M_TOT / GBM), 256, SMEM_MMA>>>(
        c_hi, c_mid, wo_hi, wo_mid, b_out, out, HIDDEN);
}

// round 17
// speedup vs baseline: 1.9600x; 1.9600x over previous
#include <cuda_runtime.h>
#include <cuda_bf16.h>
#include <math_constants.h>
#include <cstdint>

// Problem constants
#define BATCH   2
#define SEQ     2048
#define HIDDEN  1024
#define HEADS   16
#define HEAD_D  64
#define QKV_N   (3 * HIDDEN)          // 3072
#define M_TOT   (BATCH * SEQ)         // 4096
#define KDIM    1024
#define ATTN_SCALE 125.0f             // TEMP_K / sqrt(HEAD_D)
#define BH_TOT  (BATCH * HEADS)       // 32
#define ATT_ELEMS (BH_TOT * SEQ * HEAD_D)
#define NROWS   (BH_TOT * SEQ)        // 65536
#define CAND_MARGIN 30.0f             // logit-units candidate threshold
#define MAX_CAND 24

// ---------------------------------------------------------------------------
// Scratch (__device__ globals per allocation-free rule)
// ---------------------------------------------------------------------------
__device__ float g_qkv[M_TOT * QKV_N];
__device__ __nv_bfloat16 g_x_hi[M_TOT * HIDDEN];
__device__ __nv_bfloat16 g_x_mid[M_TOT * HIDDEN];
__device__ __nv_bfloat16 g_c_hi[M_TOT * HIDDEN];
__device__ __nv_bfloat16 g_c_mid[M_TOT * HIDDEN];
__device__ __nv_bfloat16 g_wq_hi[QKV_N * KDIM];
__device__ __nv_bfloat16 g_wq_mid[QKV_N * KDIM];
__device__ __nv_bfloat16 g_wo_hi[HIDDEN * KDIM];
__device__ __nv_bfloat16 g_wo_mid[HIDDEN * KDIM];
__device__ __nv_bfloat16 g_aq_hi[ATT_ELEMS];   // [bh][s][64] q*125 bf16-hi
__device__ __nv_bfloat16 g_ak_hi[ATT_ELEMS];   // [bh][s][64] k bf16-hi
__device__ int g_cnt[NROWS];
__device__ int g_cand[NROWS * MAX_CAND];

// ---------------------------------------------------------------------------
__device__ __forceinline__ uint32_t smem_u32(const void* p) {
    uint32_t a;
    asm("{ .reg .u64 t; cvta.to.shared.u64 t, %1; cvt.u32.u64 %0, t; }"
        : "=r"(a) : "l"(p));
    return a;
}

__device__ __forceinline__ void cp16(uint32_t dst, const void* src) {
    asm volatile("cp.async.cg.shared.global [%0], [%1], 16;"
                 :: "r"(dst), "l"(src) : "memory");
}
#define CP_COMMIT() asm volatile("cp.async.commit_group;" ::: "memory")
#define CP_WAIT(n)  asm volatile("cp.async.wait_group %0;" :: "n"(n) : "memory")

__device__ __forceinline__ void ldsm4(uint32_t* r, uint32_t addr) {
    asm volatile("ldmatrix.sync.aligned.m8n8.x4.shared.b16 {%0,%1,%2,%3}, [%4];"
                 : "=r"(r[0]), "=r"(r[1]), "=r"(r[2]), "=r"(r[3]) : "r"(addr));
}

__device__ __forceinline__ void mma16816(float* c, const uint32_t* a,
                                         const uint32_t* b) {
    asm volatile(
        "mma.sync.aligned.m16n8k16.row.col.f32.bf16.bf16.f32 "
        "{%0,%1,%2,%3}, {%4,%5,%6,%7}, {%8,%9}, {%0,%1,%2,%3};"
        : "+f"(c[0]), "+f"(c[1]), "+f"(c[2]), "+f"(c[3])
        : "r"(a[0]), "r"(a[1]), "r"(a[2]), "r"(a[3]), "r"(b[0]), "r"(b[1]));
}

__device__ __forceinline__ void store_split2(__nv_bfloat16* hi,
                                             __nv_bfloat16* mid,
                                             size_t off, float a, float b) {
    __nv_bfloat162 h;
    h.x = __float2bfloat16_rn(a);
    h.y = __float2bfloat16_rn(b);
    *(__nv_bfloat162*)(hi + off) = h;
    __nv_bfloat162 m2 = __floats2bfloat162_rn(a - __bfloat162float(h.x),
                                              b - __bfloat162float(h.y));
    *(__nv_bfloat162*)(mid + off) = m2;
}

// ---------------------------------------------------------------------------
// Prepass 0: zero candidate counters.
// ---------------------------------------------------------------------------
__global__ __launch_bounds__(256)
void zero_cnt(int* __restrict__ cnt)
{
    int i = blockIdx.x * 256 + threadIdx.x;
    if (i < NROWS) cnt[i] = 0;
}

// ---------------------------------------------------------------------------
// Prepass 1: elementwise fp32 -> bf16 (hi, mid) split.
// ---------------------------------------------------------------------------
__global__ __launch_bounds__(256)
void split_rows(const float4* __restrict__ src,
                __nv_bfloat162* __restrict__ hi,
                __nv_bfloat162* __restrict__ mid, int n4)
{
    int i = blockIdx.x * blockDim.x + threadIdx.x;
    if (i >= n4) return;
    float4 v = src[i];
    __nv_bfloat16 h0 = __float2bfloat16_rn(v.x);
    __nv_bfloat16 h1 = __float2bfloat16_rn(v.y);
    __nv_bfloat16 h2 = __float2bfloat16_rn(v.z);
    __nv_bfloat16 h3 = __float2bfloat16_rn(v.w);
    __nv_bfloat16 m0 = __float2bfloat16_rn(v.x - __bfloat162float(h0));
    __nv_bfloat16 m1 = __float2bfloat16_rn(v.y - __bfloat162float(h1));
    __nv_bfloat16 m2 = __float2bfloat16_rn(v.z - __bfloat162float(h2));
    __nv_bfloat16 m3 = __float2bfloat16_rn(v.w - __bfloat162float(h3));
    __nv_bfloat162 a, b, c, d;
    a.x = h0; a.y = h1; b.x = h2; b.y = h3;
    c.x = m0; c.y = m1; d.x = m2; d.y = m3;
    hi[2 * i] = a;  hi[2 * i + 1] = b;
    mid[2 * i] = c; mid[2 * i + 1] = d;
}

// ---------------------------------------------------------------------------
// Prepass 2: W [K x N] fp32 -> W^T [N x K] bf16 (hi, mid).
// ---------------------------------------------------------------------------
__global__ __launch_bounds__(256)
void split_transpose(const float* __restrict__ W,
                     __nv_bfloat16* __restrict__ hi,
                     __nv_bfloat16* __restrict__ mid, int K, int N)
{
    __shared__ float s[32][33];
    int n0 = blockIdx.x * 32;
    int k0 = blockIdx.y * 32;
    int tx = threadIdx.x, ty = threadIdx.y;
    #pragma unroll
    for (int i = 0; i < 4; i++) {
        int kk = ty + 8 * i;
        s[kk][tx] = W[(size_t)(k0 + kk) * N + n0 + tx];
    }
    __syncthreads();
    #pragma unroll
    for (int i = 0; i < 4; i++) {
        int nn = ty + 8 * i;
        float v = s[tx][nn];
        __nv_bfloat16 h = __float2bfloat16_rn(v);
        __nv_bfloat16 m = __float2bfloat16_rn(v - __bfloat162float(h));
        size_t o = (size_t)(n0 + nn) * KDIM + k0 + tx;
        hi[o] = h;
        mid[o] = m;
    }
}

// ---------------------------------------------------------------------------
// Prepass 3 (slim): qkv fp32 -> bf16-hi Q (x125) and K only.
// ---------------------------------------------------------------------------
__global__ __launch_bounds__(256)
void attn_prep2(const float* __restrict__ qkv,
                __nv_bfloat16* __restrict__ qh, __nv_bfloat16* __restrict__ kh)
{
    int st = blockIdx.x * 64;
    int h  = blockIdx.y;
    int b  = blockIdx.z;
    int bh = b * HEADS + h;
    int t  = threadIdx.x;
    #pragma unroll
    for (int i = 0; i < 16; i++) {
        int e   = t + 256 * i;       // 0..4095
        int row = e >> 6;
        int d   = e & 63;
        const float* base = qkv + (size_t)(b * SEQ + st + row) * QKV_N + h * HEAD_D + d;
        size_t o = ((size_t)bh * SEQ + st + row) * HEAD_D + d;
        qh[o] = __float2bfloat16_rn(base[0] * ATTN_SCALE);
        kh[o] = __float2bfloat16_rn(base[HIDDEN]);
    }
}

// ---------------------------------------------------------------------------
// mma.sync split-bf16 GEMM (exact round-14 version: measured 239us QKV).
// ---------------------------------------------------------------------------
#define GBM 128
#define GBN 128
#define GBK 32
#define ROWB 80
#define TILE_SZ (128 * ROWB)
#define STAGE_SZ (4 * TILE_SZ)
#define SMEM_MMA (2 * STAGE_SZ)

__device__ __forceinline__ void load_tile_async(uint32_t dst,
                                                const __nv_bfloat16* src,
                                                int row0, int k0, int t)
{
    #pragma unroll
    for (int f = t; f < 512; f += 256) {
        int row = f >> 2, q = f & 3;
        cp16(dst + row * ROWB + q * 16,
             src + (size_t)(row0 + row) * KDIM + k0 + q * 8);
    }
}

__global__ __launch_bounds__(256, 2)
void mma_gemm(const __nv_bfloat16* __restrict__ Ahi,
              const __nv_bfloat16* __restrict__ Amid,
              const __nv_bfloat16* __restrict__ Bhi,
              const __nv_bfloat16* __restrict__ Bmid,
              const float* __restrict__ bias, float* __restrict__ C, int ldN)
{
    extern __shared__ char smraw[];
    uint32_t sb = smem_u32(smraw);

    int t    = threadIdx.x;
    int lane = t & 31;
    int wid  = t >> 5;
    int wm   = wid & 3;
    int wn   = wid >> 2;
    int m0   = blockIdx.y * GBM;
    int n0   = blockIdx.x * GBN;

    int g  = lane >> 3;
    int lr = lane & 7;
    int aRow = ((g & 1) << 3) + lr;
    int aCol = (g >> 1) << 4;
    int bRow = ((g >> 1) << 3) + lr;
    int bCol = (g & 1) << 4;

    float c[2][8][4];
    #pragma unroll
    for (int mi = 0; mi < 2; mi++)
        #pragma unroll
        for (int ng = 0; ng < 8; ng++)
            #pragma unroll
            for (int j = 0; j < 4; j++) c[mi][ng][j] = 0.0f;

    const int NCH = KDIM / GBK;

    {
        uint32_t st = sb;
        load_tile_async(st,               Ahi,  m0, 0, t);
        load_tile_async(st + TILE_SZ,     Amid, m0, 0, t);
        load_tile_async(st + 2 * TILE_SZ, Bhi,  n0, 0, t);
        load_tile_async(st + 3 * TILE_SZ, Bmid, n0, 0, t);
        CP_COMMIT();
    }

    #pragma unroll 1
    for (int i = 0; i < NCH; i++) {
        uint32_t cur = sb + (i & 1) * STAGE_SZ;
        if (i + 1 < NCH) {
            uint32_t nst = sb + ((i + 1) & 1) * STAGE_SZ;
            int k0 = (i + 1) * GBK;
            load_tile_async(nst,               Ahi,  m0, k0, t);
            load_tile_async(nst + TILE_SZ,     Amid, m0, k0, t);
            load_tile_async(nst + 2 * TILE_SZ, Bhi,  n0, k0, t);
            load_tile_async(nst + 3 * TILE_SZ, Bmid, n0, k0, t);
            CP_COMMIT();
            CP_WAIT(1);
        } else {
            CP_WAIT(0);
        }
        __syncthreads();

        uint32_t AhiB = cur;
        uint32_t AmdB = cur + TILE_SZ;
        uint32_t BhiB = cur + 2 * TILE_SZ;
        uint32_t BmdB = cur + 3 * TILE_SZ;

        #pragma unroll
        for (int ks = 0; ks < 2; ks++) {
            int kb = ks * 32;
            uint32_t aH[2][4], aM[2][4];
            #pragma unroll
            for (int mi = 0; mi < 2; mi++)
                ldsm4(aH[mi], AhiB + (wm * 32 + mi * 16 + aRow) * ROWB + kb + aCol);
            #pragma unroll
            for (int mi = 0; mi < 2; mi++)
                ldsm4(aM[mi], AmdB + (wm * 32 + mi * 16 + aRow) * ROWB + kb + aCol);

            #pragma unroll
            for (int nh = 0; nh < 2; nh++) {
                uint32_t bH[2][4], bM[2][4];
                #pragma unroll
                for (int nb = 0; nb < 2; nb++)
                    ldsm4(bH[nb], BhiB + (wn * 64 + nh * 32 + nb * 16 + bRow) * ROWB + kb + bCol);
                #pragma unroll
                for (int nb = 0; nb < 2; nb++)
                    ldsm4(bM[nb], BmdB + (wn * 64 + nh * 32 + nb * 16 + bRow) * ROWB + kb + bCol);

                #pragma unroll
                for (int mi = 0; mi < 2; mi++)
                    #pragma unroll
                    for (int ng = 0; ng < 4; ng++)
                        mma16816(c[mi][nh * 4 + ng], aH[mi],
                                 &bH[ng >> 1][(ng & 1) * 2]);
                #pragma unroll
                for (int mi = 0; mi < 2; mi++)
                    #pragma unroll
                    for (int ng = 0; ng < 4; ng++)
                        mma16816(c[mi][nh * 4 + ng], aH[mi],
                                 &bM[ng >> 1][(ng & 1) * 2]);
                #pragma unroll
                for (int mi = 0; mi < 2; mi++)
                    #pragma unroll
                    for (int ng = 0; ng < 4; ng++)
                        mma16816(c[mi][nh * 4 + ng], aM[mi],
                                 &bH[ng >> 1][(ng & 1) * 2]);
            }
        }
        __syncthreads();
    }

    int r  = lane >> 2;
    int cg = (lane & 3) * 2;
    #pragma unroll
    for (int mi = 0; mi < 2; mi++) {
        #pragma unroll
        for (int ng = 0; ng < 8; ng++) {
            int gn  = n0 + wn * 64 + ng * 8 + cg;
            float2 bb = *(const float2*)(bias + gn);
            int gm  = m0 + wm * 32 + mi * 16 + r;
            float2 o0, o1;
            o0.x = c[mi][ng][0] + bb.x;  o0.y = c[mi][ng][1] + bb.y;
            o1.x = c[mi][ng][2] + bb.x;  o1.y = c[mi][ng][3] + bb.y;
            *(float2*)(C + (size_t)gm * ldN + gn)       = o0;
            *(float2*)(C + (size_t)(gm + 8) * ldN + gn) = o1;
        }
    }
}

// ---------------------------------------------------------------------------
// Attention phase 1 (single pass): hh-logit scan with inline candidate
// flagging against the RUNNING row max (superset of true candidates).
// ---------------------------------------------------------------------------
#define AP 144
#define SQ_SZ  (128 * AP)              // 18432 (Q hi)
#define SK_SZ  (64 * AP)               // 9216 per K tile
#define SO_K0   SQ_SZ
#define SO_K1   (SQ_SZ + SK_SZ)
#define SMEM_SCAN (SQ_SZ + 2 * SK_SZ)

__device__ __forceinline__ void load_k_tile(uint32_t dst,
    const __nv_bfloat16* kh, int bh, int k0, int t)
{
    #pragma unroll
    for (int i = 0; i < 2; i++) {
        int f = t + 256 * i;
        int row = f >> 3, ch = f & 7;
        cp16(dst + row * AP + ch * 16,
             kh + ((size_t)bh * SEQ + k0 + row) * HEAD_D + ch * 8);
    }
}

__global__ __launch_bounds__(256)
void attn_scan(const __nv_bfloat16* __restrict__ qhp,
               const __nv_bfloat16* __restrict__ khp)
{
    extern __shared__ char smraw[];
    uint32_t sb = smem_u32(smraw);

    int qt = (int)gridDim.x - 1 - (int)blockIdx.x;
    int h  = blockIdx.y;
    int b  = blockIdx.z;
    int bh = b * HEADS + h;
    int q0 = qt * 128;
    int t    = threadIdx.x;
    int lane = t & 31;
    int wid  = t >> 5;

    int g  = lane >> 3;
    int lr = lane & 7;
    int aRow = ((g & 1) << 3) + lr;
    int aCol = (g >> 1) << 4;
    int bRow = ((g >> 1) << 3) + lr;
    int bCol = (g & 1) << 4;

    // load Q hi
    {
        const __nv_bfloat16* p = qhp + ((size_t)bh * SEQ + q0) * HEAD_D;
        #pragma unroll
        for (int i = 0; i < 4; i++) {
            int f = t + 256 * i;
            int row = f >> 3, chq = f & 7;
            cp16(sb + row * AP + chq * 16, p + row * HEAD_D + chq * 8);
        }
        CP_COMMIT();
    }
    load_k_tile(sb + SO_K0, khp, bh, 0, t);
    CP_COMMIT();
    CP_WAIT(1);
    __syncthreads();

    uint32_t qfh[4][4];
    #pragma unroll
    for (int ks = 0; ks < 4; ks++)
        ldsm4(qfh[ks], sb + (wid * 16 + aRow) * AP + ks * 32 + aCol);

    float m0 = -CUDART_INF_F, m1 = -CUDART_INF_F;   // per-row running max
    int r0g  = q0 + wid * 16 + (lane >> 2);
    int rtop = q0 + wid * 16 + 15;
    int grow0 = bh * SEQ + r0g;
    int grow1 = grow0 + 8;
    const int nkt = qt * 2 + 2;

    #pragma unroll 1
    for (int kt = 0; kt < nkt; kt++) {
        uint32_t cur = sb + ((kt & 1) ? SO_K1 : SO_K0);
        if (kt + 1 < nkt) {
            load_k_tile(sb + (((kt + 1) & 1) ? SO_K1 : SO_K0), khp, bh,
                        (kt + 1) * 64, t);
            CP_COMMIT();
            CP_WAIT(1);
        } else {
            CP_WAIT(0);
        }
        __syncthreads();

        if (kt * 64 <= rtop) {           // warp-uniform: not fully masked
            float s[8][4];
            #pragma unroll
            for (int nb = 0; nb < 8; nb++)
                #pragma unroll
                for (int j = 0; j < 4; j++) s[nb][j] = 0.0f;
            #pragma unroll
            for (int ks = 0; ks < 4; ks++) {
                uint32_t bk[4][4];
                #pragma unroll
                for (int n4 = 0; n4 < 4; n4++)
                    ldsm4(bk[n4], cur + (n4 * 16 + bRow) * AP + ks * 32 + bCol);
                #pragma unroll
                for (int nb = 0; nb < 8; nb++)
                    mma16816(s[nb], qfh[ks], &bk[nb >> 1][(nb & 1) * 2]);
            }
            if (kt * 64 + 63 > q0 + wid * 16) {
                #pragma unroll
                for (int nb = 0; nb < 8; nb++) {
                    int gc = kt * 64 + nb * 8 + (lane & 3) * 2;
                    if (gc + 0 > r0g)     s[nb][0] = -CUDART_INF_F;
                    if (gc + 1 > r0g)     s[nb][1] = -CUDART_INF_F;
                    if (gc + 0 > r0g + 8) s[nb][2] = -CUDART_INF_F;
                    if (gc + 1 > r0g + 8) s[nb][3] = -CUDART_INF_F;
                }
            }
            // update running row maxes
            float tm0 = -CUDART_INF_F, tm1 = -CUDART_INF_F;
            #pragma unroll
            for (int nb = 0; nb < 8; nb++) {
                tm0 = fmaxf(tm0, fmaxf(s[nb][0], s[nb][1]));
                tm1 = fmaxf(tm1, fmaxf(s[nb][2], s[nb][3]));
            }
            tm0 = fmaxf(tm0, __shfl_xor_sync(0xffffffffu, tm0, 1));
            tm0 = fmaxf(tm0, __shfl_xor_sync(0xffffffffu, tm0, 2));
            tm1 = fmaxf(tm1, __shfl_xor_sync(0xffffffffu, tm1, 1));
            tm1 = fmaxf(tm1, __shfl_xor_sync(0xffffffffu, tm1, 2));
            m0 = fmaxf(m0, tm0);
            m1 = fmaxf(m1, tm1);

            // flag candidates vs running max (superset of true candidates)
            float th0 = m0 - CAND_MARGIN;
            float th1 = m1 - CAND_MARGIN;
            #pragma unroll
            for (int nb = 0; nb < 8; nb++) {
                int kbase = kt * 64 + nb * 8 + (lane & 3) * 2;
                if (s[nb][0] >= th0) {
                    int idx = atomicAdd(&g_cnt[grow0], 1);
                    if (idx < MAX_CAND) g_cand[grow0 * MAX_CAND + idx] = kbase;
                }
                if (s[nb][1] >= th0) {
                    int idx = atomicAdd(&g_cnt[grow0], 1);
                    if (idx < MAX_CAND) g_cand[grow0 * MAX_CAND + idx] = kbase + 1;
                }
                if (s[nb][2] >= th1) {
                    int idx = atomicAdd(&g_cnt[grow1], 1);
                    if (idx < MAX_CAND) g_cand[grow1 * MAX_CAND + idx] = kbase;
                }
                if (s[nb][3] >= th1) {
                    int idx = atomicAdd(&g_cnt[grow1], 1);
                    if (idx < MAX_CAND) g_cand[grow1 * MAX_CAND + idx] = kbase + 1;
                }
            }
        }
        __syncthreads();
    }
}

// ---------------------------------------------------------------------------
// Attention phase 2: exact fp32 softmax over candidates.
// One warp per row. Candidates held one-per-lane, canonically ordered by a
// warp bitonic sort (15 shfl steps); online softmax over the sorted list
// (broadcast via shfl). No per-thread arrays -> no spills; deterministic.
// ---------------------------------------------------------------------------
__global__ __launch_bounds__(256)
void attn_gather(const float* __restrict__ qkv,
                 __nv_bfloat16* __restrict__ ch,
                 __nv_bfloat16* __restrict__ cm)
{
    int w    = (blockIdx.x * 256 + threadIdx.x) >> 5;   // global row
    int lane = threadIdx.x & 31;
    int bh = w >> 11;
    int sq = w & (SEQ - 1);
    int b  = bh >> 4;
    int h  = bh & 15;

    const float* qb = qkv + ((size_t)(b * SEQ + sq)) * QKV_N + h * HEAD_D;
    float q0 = qb[lane * 2]     * ATTN_SCALE;
    float q1 = qb[lane * 2 + 1] * ATTN_SCALE;

    int cnt = g_cnt[w];
    if (cnt > MAX_CAND) cnt = MAX_CAND;

    size_t off = (size_t)(b * SEQ + sq) * HIDDEN + h * HEAD_D + lane * 2;
    if (cnt <= 0) {              // defensive (argmax key always flagged)
        store_split2(ch, cm, off, 0.0f, 0.0f);
        return;
    }

    // one candidate per lane; pad with INT_MAX
    int v = (lane < cnt) ? g_cand[w * MAX_CAND + lane] : 0x7fffffff;

    // warp bitonic sort, ascending across lanes (canonical order)
    #pragma unroll
    for (int k = 2; k <= 32; k <<= 1) {
        #pragma unroll
        for (int j = k >> 1; j > 0; j >>= 1) {
            int p = __shfl_xor_sync(0xffffffffu, v, j);
            bool up = ((lane & k) == 0);
            bool lowhalf = ((lane & j) == 0);
            bool takeMin = (lowhalf == up);
            v = takeMin ? min(v, p) : max(v, p);
        }
    }

    // online softmax over sorted candidates (exact fp32 logits)
    float m = -CUDART_INF_F, l = 0.0f, o0 = 0.0f, o1 = 0.0f;
    #pragma unroll 1
    for (int i = 0; i < cnt; i++) {
        int cdi = __shfl_sync(0xffffffffu, v, i);
        const float* kb = qkv + ((size_t)(b * SEQ + cdi)) * QKV_N
                        + HIDDEN + h * HEAD_D;
        float p = q0 * kb[lane * 2] + q1 * kb[lane * 2 + 1];
        p += __shfl_xor_sync(0xffffffffu, p, 16);
        p += __shfl_xor_sync(0xffffffffu, p, 8);
        p += __shfl_xor_sync(0xffffffffu, p, 4);
        p += __shfl_xor_sync(0xffffffffu, p, 2);
        p += __shfl_xor_sync(0xffffffffu, p, 1);

        float mn   = fmaxf(m, p);
        float corr = __expf(m - mn);    // 0 on first iteration
        float pe   = __expf(p - mn);
        const float* vb = qkv + ((size_t)(b * SEQ + cdi)) * QKV_N
                        + 2 * HIDDEN + h * HEAD_D;
        l  = l  * corr + pe;
        o0 = o0 * corr + pe * vb[lane * 2];
        o1 = o1 * corr + pe * vb[lane * 2 + 1];
        m = mn;
    }
    float inv = 1.0f / l;
    store_split2(ch, cm, off, o0 * inv, o1 * inv);
}

// ---------------------------------------------------------------------------
extern "C" void kernel_launch(void* const* d_in, const int* in_sizes, int n_in,
                              void* d_out, int out_size)
{
    const float* x     = (const float*)d_in[0];
    const float* W_qkv = (const float*)d_in[1];
    const float* b_qkv = (const float*)d_in[2];
    const float* W_out = (const float*)d_in[3];
    const float* b_out = (const float*)d_in[4];
    float* out = (float*)d_out;

    float *qkv;
    __nv_bfloat16 *x_hi, *x_mid, *c_hi, *c_mid, *wq_hi, *wq_mid, *wo_hi, *wo_mid;
    __nv_bfloat16 *aqh, *akh;
    int* cnt_ptr;
    cudaGetSymbolAddress((void**)&qkv,    g_qkv);
    cudaGetSymbolAddress((void**)&x_hi,   g_x_hi);
    cudaGetSymbolAddress((void**)&x_mid,  g_x_mid);
    cudaGetSymbolAddress((void**)&c_hi,   g_c_hi);
    cudaGetSymbolAddress((void**)&c_mid,  g_c_mid);
    cudaGetSymbolAddress((void**)&wq_hi,  g_wq_hi);
    cudaGetSymbolAddress((void**)&wq_mid, g_wq_mid);
    cudaGetSymbolAddress((void**)&wo_hi,  g_wo_hi);
    cudaGetSymbolAddress((void**)&wo_mid, g_wo_mid);
    cudaGetSymbolAddress((void**)&aqh,    g_aq_hi);
    cudaGetSymbolAddress((void**)&akh,    g_ak_hi);
    cudaGetSymbolAddress((void**)&cnt_ptr, g_cnt);

    cudaFuncSetAttribute(mma_gemm, cudaFuncAttributeMaxDynamicSharedMemorySize,
                         SMEM_MMA);
    cudaFuncSetAttribute(attn_scan, cudaFuncAttributeMaxDynamicSharedMemorySize,
                         SMEM_SCAN);

    // 0) zero candidate counters
    zero_cnt<<<(NROWS + 255) / 256, 256>>>(cnt_ptr);
    // 1) split x -> bf16 hi/mid
    {
        int n4 = M_TOT * HIDDEN / 4;
        split_rows<<<(n4 + 255) / 256, 256>>>((const float4*)x,
                                              (__nv_bfloat162*)x_hi,
                                              (__nv_bfloat162*)x_mid, n4);
    }
    // 2) transpose+split W_qkv
    split_transpose<<<dim3(QKV_N / 32, KDIM / 32), dim3(32, 8)>>>(
        W_qkv, wq_hi, wq_mid, KDIM, QKV_N);
    // 3) QKV projection (tensor cores, 2 CTAs/SM — round-14 schedule)
    mma_gemm<<<dim3(QKV_N / GBN, M_TOT / GBM), 256, SMEM_MMA>>>(
        x_hi, x_mid, wq_hi, wq_mid, b_qkv, qkv, QKV_N);
    // 4) prep bf16-hi Q/K
    attn_prep2<<<dim3(SEQ / 64, HEADS, BATCH), 256>>>(qkv, aqh, akh);
    // 5) phase 1: single-pass scan + candidate flagging
    attn_scan<<<dim3(SEQ / 128, HEADS, BATCH), 256, SMEM_SCAN>>>(aqh, akh);
    // 6) phase 2: exact softmax over candidates -> ctx hi/mid
    attn_gather<<<NROWS / 8, 256>>>(qkv, c_hi, c_mid);
    // 7) transpose+split W_out
    split_transpose<<<dim3(HIDDEN / 32, KDIM / 32), dim3(32, 8)>>>(
        W_out, wo_hi, wo_mid, KDIM, HIDDEN);
    // 8) output projection (tensor cores, 2 CTAs/SM)
    mma_gemm<<<dim3(HIDDEN / GBN, M_TOT / GBM), 256, SMEM_MMA>>>(
        c_hi, c_mid, wo_hi, wo_mid, b_out, out, HIDDEN);
}